// round 1
// baseline (speedup 1.0000x reference)
#include <cuda_runtime.h>
#include <cstdint>
#include <math.h>

#define BB 128
#define LL 50
#define NN 12
#define N2N 12
#define SS 20
#define MM 12
#define DD 100

// ---------------- device scratch (no allocations allowed) ----------------
__device__ __align__(16) float g_emb1[BB * LL * DD];        // 640,000
__device__ __align__(16) float g_emb2[BB * LL * DD];        // 640,000
__device__ __align__(16) float g_sn2[BB * LL * NN * DD];    // 7,680,000
__device__ __align__(16) float g_t1[BB * SS * DD];          // 256,000
__device__ __align__(16) float g_t2[BB * SS * DD];          // 256,000

typedef unsigned long long ull;

__device__ __forceinline__ ull pk2(float lo, float hi) {
    ull r; asm("mov.b64 %0,{%1,%2};" : "=l"(r) : "f"(lo), "f"(hi)); return r;
}
__device__ __forceinline__ void upk2(ull v, float& lo, float& hi) {
    asm("mov.b64 {%0,%1},%2;" : "=f"(lo), "=f"(hi) : "l"(v));
}
__device__ __forceinline__ ull ffma2(ull a, ull b, ull c) {
    ull d; asm("fma.rn.f32x2 %0,%1,%2,%3;" : "=l"(d) : "l"(a), "l"(b), "l"(c)); return d;
}
__device__ __forceinline__ float warp_sum(float v) {
#pragma unroll
    for (int off = 16; off; off >>= 1) v += __shfl_down_sync(0xffffffffu, v, off);
    return v;
}

// ===========================================================================
// Session / 2-hop neighbor attention (generic):
//   per unit u: a = selfv[u] (D), V = neigh[u] (NNxD)
//   X[n] = a .* V[n];  h = leaky(X @ W1, 0.2);  s[n] = h[n] . w2
//   att = softmax_n(s);  out = sum_n att[n] * V[n]  (optionally l2-normalized)
// Block: 128 threads, thread j<100 owns output column j, 6 packed f32x2
// accumulators over the 12 neighbors. W1 cached in smem per block.
// ===========================================================================
template <bool NORM, int UPB>
__global__ void __launch_bounds__(128) sess_att_kernel(
    const float* __restrict__ selfv, const float* __restrict__ neigh,
    const float* __restrict__ W1, const float* __restrict__ w2,
    float* __restrict__ outv, int nunits)
{
    extern __shared__ float sm[];
    float* W1s  = sm;             // 10000
    float* w2s  = sm + 10000;     // 104
    float* As   = sm + 10104;     // 104
    float* Vs   = sm + 10208;     // 1200
    float* Xt   = sm + 11408;     // 100*16 (16B-aligned: 11408*4 % 16 == 0)
    float* redS = sm + 13008;     // 48
    float* scS  = sm + 13056;     // 12
    float* red2 = sm + 13068;     // 4   -> total 13072 floats = 52288 B

    const int tid = threadIdx.x;
    const int lane = tid & 31, warp = tid >> 5;

    for (int i = tid; i < DD * DD; i += 128) W1s[i] = W1[i];
    if (tid < DD) w2s[tid] = w2[tid];
    __syncthreads();

    const int u0 = blockIdx.x * UPB;
    const int u1 = min(u0 + UPB, nunits);
    for (int u = u0; u < u1; ++u) {
        const float* sv = selfv + (size_t)u * DD;
        const float* ng = neigh + (size_t)u * (NN * DD);
        if (tid < DD) As[tid] = sv[tid];
        for (int i = tid; i < NN * DD; i += 128) Vs[i] = ng[i];
        __syncthreads();
        // transposed product tile: Xt[d*16+n] = a[d]*V[n][d]
        for (int i = tid; i < NN * DD; i += 128) {
            int d = i / NN, n = i - d * NN;
            Xt[d * 16 + n] = As[d] * Vs[n * DD + d];
        }
        __syncthreads();

        float p[NN];
        const int j = tid;
        if (j < DD) {
            ull a0 = 0, a1 = 0, a2 = 0, a3 = 0, a4 = 0, a5 = 0;
#pragma unroll 4
            for (int d = 0; d < DD; ++d) {
                float w = W1s[d * DD + j];
                ull ww = pk2(w, w);
                const ulonglong2* xp = reinterpret_cast<const ulonglong2*>(Xt + d * 16);
                ulonglong2 xa = xp[0], xb = xp[1], xc = xp[2];
                a0 = ffma2(xa.x, ww, a0);
                a1 = ffma2(xa.y, ww, a1);
                a2 = ffma2(xb.x, ww, a2);
                a3 = ffma2(xb.y, ww, a3);
                a4 = ffma2(xc.x, ww, a4);
                a5 = ffma2(xc.y, ww, a5);
            }
            const float w2j = w2s[j];
            ull accs[6] = {a0, a1, a2, a3, a4, a5};
#pragma unroll
            for (int q = 0; q < 6; q++) {
                float h0, h1;
                upk2(accs[q], h0, h1);
                h0 = (h0 > 0.f) ? h0 : 0.2f * h0;
                h1 = (h1 > 0.f) ? h1 : 0.2f * h1;
                p[2 * q]     = h0 * w2j;
                p[2 * q + 1] = h1 * w2j;
            }
        } else {
#pragma unroll
            for (int n = 0; n < NN; n++) p[n] = 0.f;
        }
        // score[n] = sum_j p[n][j]
#pragma unroll
        for (int n = 0; n < NN; n++) {
            float v = warp_sum(p[n]);
            if (lane == 0) redS[n * 4 + warp] = v;
        }
        __syncthreads();
        if (tid < NN)
            scS[tid] = redS[tid * 4] + redS[tid * 4 + 1] + redS[tid * 4 + 2] + redS[tid * 4 + 3];
        __syncthreads();
        // softmax over 12 (computed redundantly by all threads)
        float att[NN];
        {
            float mx = scS[0];
#pragma unroll
            for (int n = 1; n < NN; n++) mx = fmaxf(mx, scS[n]);
            float ssum = 0.f;
#pragma unroll
            for (int n = 0; n < NN; n++) { att[n] = __expf(scS[n] - mx); ssum += att[n]; }
            float inv = 1.f / ssum;
#pragma unroll
            for (int n = 0; n < NN; n++) att[n] *= inv;
        }
        float tot = 0.f;
        if (j < DD) {
#pragma unroll
            for (int n = 0; n < NN; n++) tot = fmaf(att[n], Vs[n * DD + j], tot);
        }
        if (NORM) {
            float sq = warp_sum(tot * tot);
            if (lane == 0) red2[warp] = sq;
            __syncthreads();
            float nrm = sqrtf(red2[0] + red2[1] + red2[2] + red2[3]);
            float scale = 1.f / fmaxf(nrm, 1e-12f);
            if (j < DD) outv[(size_t)u * DD + j] = tot * scale;
        } else {
            if (j < DD) outv[(size_t)u * DD + j] = tot;
        }
        __syncthreads();  // protect shared reuse for next unit
    }
}

// ===========================================================================
// Target neighbor attention:
//   per unit u=(b,s): t=t_in[u], sl=sl_base[b*L*D] (row l=0), V=tneigh[u]
//   cat[m] = [ t .* V[m] , sl + V[m] ] (2D)
//   a = softmax_m( tanh(cat @ W3) . w4 )
//   out = l2norm( (sum_m a[m] V[m] + t0[u]) * 0.5 )
// ===========================================================================
template <int UPB>
__global__ void __launch_bounds__(128) tar_att_kernel(
    const float* __restrict__ t_in, const float* __restrict__ sl_base,
    const float* __restrict__ tneigh, const float* __restrict__ t0v,
    const float* __restrict__ W3, const float* __restrict__ w4,
    float* __restrict__ outv, int nunits)
{
    extern __shared__ float sm[];
    float* W3s  = sm;             // 20000
    float* w4s  = sm + 20000;     // 104
    float* Ts   = sm + 20104;     // 104
    float* Ls   = sm + 20208;     // 104
    float* T0s  = sm + 20312;     // 104
    float* Vs   = sm + 20416;     // 1200
    float* Xt   = sm + 21616;     // 200*16 (16B aligned)
    float* redS = sm + 24816;     // 48
    float* scS  = sm + 24864;     // 12
    float* red2 = sm + 24876;     // 4 -> total 24880 floats = 99520 B

    const int tid = threadIdx.x;
    const int lane = tid & 31, warp = tid >> 5;

    for (int i = tid; i < 2 * DD * DD; i += 128) W3s[i] = W3[i];
    if (tid < DD) w4s[tid] = w4[tid];
    __syncthreads();

    const int u0 = blockIdx.x * UPB;
    const int u1 = min(u0 + UPB, nunits);
    for (int u = u0; u < u1; ++u) {
        const int b = u / SS;
        if (tid < DD) {
            Ts[tid]  = t_in[(size_t)u * DD + tid];
            Ls[tid]  = sl_base[(size_t)b * (LL * DD) + tid];
            T0s[tid] = t0v[(size_t)u * DD + tid];
        }
        const float* ng = tneigh + (size_t)u * (MM * DD);
        for (int i = tid; i < MM * DD; i += 128) Vs[i] = ng[i];
        __syncthreads();
        for (int i = tid; i < 2 * DD * MM; i += 128) {
            int k = i / MM, m = i - k * MM;
            float v = (k < DD) ? (Ts[k] * Vs[m * DD + k])
                               : (Ls[k - DD] + Vs[m * DD + (k - DD)]);
            Xt[k * 16 + m] = v;
        }
        __syncthreads();

        float p[MM];
        const int j = tid;
        if (j < DD) {
            ull a0 = 0, a1 = 0, a2 = 0, a3 = 0, a4 = 0, a5 = 0;
#pragma unroll 4
            for (int k = 0; k < 2 * DD; ++k) {
                float w = W3s[k * DD + j];
                ull ww = pk2(w, w);
                const ulonglong2* xp = reinterpret_cast<const ulonglong2*>(Xt + k * 16);
                ulonglong2 xa = xp[0], xb = xp[1], xc = xp[2];
                a0 = ffma2(xa.x, ww, a0);
                a1 = ffma2(xa.y, ww, a1);
                a2 = ffma2(xb.x, ww, a2);
                a3 = ffma2(xb.y, ww, a3);
                a4 = ffma2(xc.x, ww, a4);
                a5 = ffma2(xc.y, ww, a5);
            }
            const float w4j = w4s[j];
            ull accs[6] = {a0, a1, a2, a3, a4, a5};
#pragma unroll
            for (int q = 0; q < 6; q++) {
                float h0, h1;
                upk2(accs[q], h0, h1);
                p[2 * q]     = tanhf(h0) * w4j;
                p[2 * q + 1] = tanhf(h1) * w4j;
            }
        } else {
#pragma unroll
            for (int m = 0; m < MM; m++) p[m] = 0.f;
        }
#pragma unroll
        for (int m = 0; m < MM; m++) {
            float v = warp_sum(p[m]);
            if (lane == 0) redS[m * 4 + warp] = v;
        }
        __syncthreads();
        if (tid < MM)
            scS[tid] = redS[tid * 4] + redS[tid * 4 + 1] + redS[tid * 4 + 2] + redS[tid * 4 + 3];
        __syncthreads();
        float att[MM];
        {
            float mx = scS[0];
#pragma unroll
            for (int m = 1; m < MM; m++) mx = fmaxf(mx, scS[m]);
            float ssum = 0.f;
#pragma unroll
            for (int m = 0; m < MM; m++) { att[m] = __expf(scS[m] - mx); ssum += att[m]; }
            float inv = 1.f / ssum;
#pragma unroll
            for (int m = 0; m < MM; m++) att[m] *= inv;
        }
        float tot = 0.f;
        if (j < DD) {
#pragma unroll
            for (int m = 0; m < MM; m++) tot = fmaf(att[m], Vs[m * DD + j], tot);
            tot = (tot + T0s[j]) * 0.5f;
        }
        float sq = warp_sum(tot * tot);
        if (lane == 0) red2[warp] = sq;
        __syncthreads();
        float nrm = sqrtf(red2[0] + red2[1] + red2[2] + red2[3]);
        float scale = 1.f / fmaxf(nrm, 1e-12f);
        if (j < DD) outv[(size_t)u * DD + j] = tot * scale;
        __syncthreads();
    }
}

// ===========================================================================
// Output assembly:
//  part 1: sess stack [3, B, S, L, D] — layer0=sess_self, 1=emb1, 2=emb2,
//          each broadcast over S.
//  part 2: tar stack  [10, B, S, D] in order [t0,t1,t0,t1,t2,t0,t1,t0,t1,t2].
// ===========================================================================
__global__ void out_kernel(const float* __restrict__ ss, const float* __restrict__ e1,
                           const float* __restrict__ e2, const float* __restrict__ t0,
                           const float* __restrict__ t1, const float* __restrict__ t2,
                           float4* __restrict__ out4)
{
    const int SESS4 = 3 * BB * SS * LL * (DD / 4);  // 9,600,000
    const int TAR4  = 10 * BB * SS * (DD / 4);      //   640,000
    int idx = blockIdx.x * blockDim.x + threadIdx.x;
    if (idx < SESS4) {
        int r = idx % 25;
        int q = idx / 25;          // ((layer*B+b)*S+s)*L + l
        int l = q % LL;
        int t = q / LL;            // (layer*B+b)*S + s
        int bb = t / SS;           // layer*B + b
        int layer = bb >> 7;
        int b = bb & (BB - 1);
        const float* src = (layer == 0) ? ss : ((layer == 1) ? e1 : e2);
        out4[idx] = reinterpret_cast<const float4*>(src + ((size_t)b * LL + l) * DD)[r];
    } else if (idx < SESS4 + TAR4) {
        int jj = idx - SESS4;
        int k = jj / (BB * SS * (DD / 4));   // 0..9
        int i = jj % (BB * SS * (DD / 4));
        int km = k % 5;                      // pattern [t0,t1,t0,t1,t2] x2
        const float* src = (km == 4) ? t2 : ((km & 1) ? t1 : t0);
        out4[idx] = reinterpret_cast<const float4*>(src)[i];
    }
}

// ===========================================================================
extern "C" void kernel_launch(void* const* d_in, const int* in_sizes, int n_in,
                              void* d_out, int out_size)
{
    const float* sess_self      = (const float*)d_in[0];  // [B,L,D]
    const float* sess_neighbor  = (const float*)d_in[1];  // [B,L,N,D]
    const float* sess_neighbor2 = (const float*)d_in[2];  // [B,L,N,N2,D]
    const float* tar_self       = (const float*)d_in[3];  // [B,S,D]
    const float* tar_neighbor   = (const float*)d_in[4];  // [B,S,M,D]
    const float* w1             = (const float*)d_in[5];  // [2,D,D]
    const float* w2             = (const float*)d_in[6];  // [2,D,1]
    const float* w3             = (const float*)d_in[7];  // [2,2D,D]
    const float* w4             = (const float*)d_in[8];  // [2,D,1]
    // d_in[9] session_len: unused by reference
    float* out = (float*)d_out;

    float *emb1, *emb2, *sn2, *t1, *t2;
    cudaGetSymbolAddress((void**)&emb1, g_emb1);
    cudaGetSymbolAddress((void**)&emb2, g_emb2);
    cudaGetSymbolAddress((void**)&sn2,  g_sn2);
    cudaGetSymbolAddress((void**)&t1,   g_t1);
    cudaGetSymbolAddress((void**)&t2,   g_t2);

    const int SMEM_SESS = 13072 * 4;  // 52,288 B -> 4 blocks/SM
    const int SMEM_TAR  = 24880 * 4;  // 99,520 B -> 2 blocks/SM
    cudaFuncSetAttribute(sess_att_kernel<true, 4>,
                         cudaFuncAttributeMaxDynamicSharedMemorySize, SMEM_SESS);
    cudaFuncSetAttribute(sess_att_kernel<false, 16>,
                         cudaFuncAttributeMaxDynamicSharedMemorySize, SMEM_SESS);
    cudaFuncSetAttribute(tar_att_kernel<4>,
                         cudaFuncAttributeMaxDynamicSharedMemorySize, SMEM_TAR);

    const int U1 = BB * LL;           // 6400
    const int U2 = BB * LL * NN;      // 76800
    const int UT = BB * SS;           // 2560

    // K1: layer-0 session attention  -> emb1 (l2-normalized)
    sess_att_kernel<true, 4><<<U1 / 4, 128, SMEM_SESS>>>(
        sess_self, sess_neighbor, w1, w2, emb1, U1);

    // K2: 2-hop aggregation (heavy)  -> sn2 (no norm)
    sess_att_kernel<false, 16><<<U2 / 16, 128, SMEM_SESS>>>(
        sess_neighbor, sess_neighbor2, w1, w2, sn2, U2);

    // K3: layer-0 target attention (sess_last = emb1[b, l=0]) -> t1
    tar_att_kernel<4><<<UT / 4, 128, SMEM_TAR>>>(
        tar_self, emb1, tar_neighbor, tar_self, w3, w4, t1, UT);

    // K4: layer-1 session attention over updated neighbors -> emb2
    sess_att_kernel<true, 4><<<U1 / 4, 128, SMEM_SESS>>>(
        emb1, sn2, w1 + DD * DD, w2 + DD, emb2, U1);

    // K5: layer-1 target attention (t = t1, sess_last = sess_self[b, l=0]) -> t2
    tar_att_kernel<4><<<UT / 4, 128, SMEM_TAR>>>(
        t1, sess_self, tar_neighbor, tar_self, w3 + 2 * DD * DD, w4 + DD, t2, UT);

    // K6: assemble output (broadcast stacks)
    const int TOT4 = 3 * BB * SS * LL * (DD / 4) + 10 * BB * SS * (DD / 4);  // 10,240,000
    out_kernel<<<(TOT4 + 255) / 256, 256>>>(sess_self, emb1, emb2,
                                            tar_self, t1, t2, (float4*)out);
}

// round 2
// speedup vs baseline: 1.3075x; 1.3075x over previous
#include <cuda_runtime.h>
#include <cstdint>
#include <math.h>

#define BB 128
#define LL 50
#define NN 12
#define SS 20
#define MM 12
#define DD 100

// ---------------- device scratch (no allocations allowed) ----------------
__device__ __align__(16) float g_emb1[BB * LL * DD];
__device__ __align__(16) float g_emb2[BB * LL * DD];
__device__ __align__(16) float g_sn2[BB * LL * NN * DD];
__device__ __align__(16) float g_t1[BB * SS * DD];
__device__ __align__(16) float g_t2[BB * SS * DD];

typedef unsigned long long ull;

__device__ __forceinline__ ull pk2(float lo, float hi) {
    ull r; asm("mov.b64 %0,{%1,%2};" : "=l"(r) : "f"(lo), "f"(hi)); return r;
}
__device__ __forceinline__ void upk2(ull v, float& lo, float& hi) {
    asm("mov.b64 {%0,%1},%2;" : "=f"(lo), "=f"(hi) : "l"(v));
}
__device__ __forceinline__ ull ffma2(ull a, ull b, ull c) {
    ull d; asm("fma.rn.f32x2 %0,%1,%2,%3;" : "=l"(d) : "l"(a), "l"(b), "l"(c)); return d;
}
__device__ __forceinline__ ull add2(ull a, ull b) {
    ull c; asm("add.rn.f32x2 %0,%1,%2;" : "=l"(c) : "l"(a), "l"(b)); return c;
}
// packed warp reduction over 32 lanes (full sum ends in lane 0)
__device__ __forceinline__ ull warp_sum2(ull v) {
#pragma unroll
    for (int off = 16; off; off >>= 1)
        v = add2(v, __shfl_down_sync(0xffffffffu, v, off));
    return v;
}

// ===========================================================================
// Session / 2-hop neighbor attention, TWO units per thread.
//   per unit u: a = selfv[u] (D), V = neigh[u] (NN x D)
//   X[n] = a .* V[n];  h = leaky(X @ W1, 0.2);  s[n] = h[n] . w2
//   att = softmax_n(s);  out = sum_n att[n]*V[n]  (opt l2-norm)
// Block: 128 threads; thread j<100 owns output column j of units A and B.
// ===========================================================================
template <bool NORM, int UPB>
__global__ void __launch_bounds__(128) sess_att_kernel(
    const float* __restrict__ selfv, const float* __restrict__ neigh,
    const float* __restrict__ W1, const float* __restrict__ w2,
    float* __restrict__ outv, int nunits)
{
    // smem layout (floats)
    extern __shared__ float sm[];
    float* W1s   = sm;            // 10000
    float* w2s   = sm + 10000;    // 104
    float* VsA   = sm + 10104;    // 1200
    float* VsB   = sm + 11304;    // 1200
    float* XtA   = sm + 12504;    // 1600 (rows of 16, 16B aligned)
    float* XtB   = sm + 14104;    // 1600
    float* attA  = sm + 15704;    // 16
    float* attB  = sm + 15720;    // 16
    float* scSA  = sm + 15736;    // 16
    float* scSB  = sm + 15752;    // 16
    float* redSA = sm + 15768;    // 48
    float* redSB = sm + 15816;    // 48
    float* red2A = sm + 15864;    // 8
    float* red2B = sm + 15872;    // 8   total 15880 floats = 63520 B

    const int tid  = threadIdx.x;
    const int lane = tid & 31, warp = tid >> 5;
    const int j = tid;

    {   // cache W1 (vectorized) + w2
        const float4* W4 = reinterpret_cast<const float4*>(W1);
        float4* W1s4 = reinterpret_cast<float4*>(W1s);
        for (int i = tid; i < DD * DD / 4; i += 128) W1s4[i] = W4[i];
        if (tid < DD) w2s[tid] = w2[tid];
    }
    __syncthreads();

    const int u0 = blockIdx.x * UPB;
    for (int u = u0; u < u0 + UPB; u += 2) {
        const int uA = u, uB = u + 1;
        // ---- load V tiles (vectorized, coalesced) ----
        {
            const float4* ngA = reinterpret_cast<const float4*>(neigh + (size_t)uA * (NN * DD));
            const float4* ngB = reinterpret_cast<const float4*>(neigh + (size_t)uB * (NN * DD));
            float4* vA4 = reinterpret_cast<float4*>(VsA);
            float4* vB4 = reinterpret_cast<float4*>(VsB);
#pragma unroll
            for (int k = 0; k < 3; k++) {
                int i = tid + k * 128;
                if (i < NN * DD / 4) { vA4[i] = ngA[i]; vB4[i] = ngB[i]; }
            }
        }
        __syncthreads();
        // ---- build transposed product tiles: Xt[d*16+n] = a[d]*V[n][d] ----
        if (tid < DD) {
            const int d = tid;
            float aA = __ldg(selfv + (size_t)uA * DD + d);
            float aB = __ldg(selfv + (size_t)uB * DD + d);
            float rA[NN], rB[NN];
#pragma unroll
            for (int n = 0; n < NN; n++) {
                rA[n] = aA * VsA[n * DD + d];
                rB[n] = aB * VsB[n * DD + d];
            }
            float4* xa = reinterpret_cast<float4*>(XtA + d * 16);
            float4* xb = reinterpret_cast<float4*>(XtB + d * 16);
            xa[0] = make_float4(rA[0], rA[1], rA[2], rA[3]);
            xa[1] = make_float4(rA[4], rA[5], rA[6], rA[7]);
            xa[2] = make_float4(rA[8], rA[9], rA[10], rA[11]);
            xb[0] = make_float4(rB[0], rB[1], rB[2], rB[3]);
            xb[1] = make_float4(rB[4], rB[5], rB[6], rB[7]);
            xb[2] = make_float4(rB[8], rB[9], rB[10], rB[11]);
        }
        __syncthreads();

        // ---- GEMM: h[:,j] for both units; 12 FFMA2 per weight load ----
        float pA[NN], pB[NN];
        if (j < DD) {
            ull aA0 = 0, aA1 = 0, aA2 = 0, aA3 = 0, aA4 = 0, aA5 = 0;
            ull aB0 = 0, aB1 = 0, aB2 = 0, aB3 = 0, aB4 = 0, aB5 = 0;
            const ulonglong2* XA = reinterpret_cast<const ulonglong2*>(XtA);
            const ulonglong2* XB = reinterpret_cast<const ulonglong2*>(XtB);
#pragma unroll 4
            for (int d = 0; d < DD; ++d) {
                float w = W1s[d * DD + j];
                ull ww = pk2(w, w);
                ulonglong2 x0 = XA[d * 4 + 0], x1 = XA[d * 4 + 1], x2 = XA[d * 4 + 2];
                ulonglong2 y0 = XB[d * 4 + 0], y1 = XB[d * 4 + 1], y2 = XB[d * 4 + 2];
                aA0 = ffma2(x0.x, ww, aA0); aA1 = ffma2(x0.y, ww, aA1);
                aA2 = ffma2(x1.x, ww, aA2); aA3 = ffma2(x1.y, ww, aA3);
                aA4 = ffma2(x2.x, ww, aA4); aA5 = ffma2(x2.y, ww, aA5);
                aB0 = ffma2(y0.x, ww, aB0); aB1 = ffma2(y0.y, ww, aB1);
                aB2 = ffma2(y1.x, ww, aB2); aB3 = ffma2(y1.y, ww, aB3);
                aB4 = ffma2(y2.x, ww, aB4); aB5 = ffma2(y2.y, ww, aB5);
            }
            const float w2j = w2s[j];
            ull accA[6] = {aA0, aA1, aA2, aA3, aA4, aA5};
            ull accB[6] = {aB0, aB1, aB2, aB3, aB4, aB5};
#pragma unroll
            for (int q = 0; q < 6; q++) {
                float h0, h1;
                upk2(accA[q], h0, h1);
                h0 = (h0 > 0.f) ? h0 : 0.2f * h0;
                h1 = (h1 > 0.f) ? h1 : 0.2f * h1;
                pA[2 * q] = h0 * w2j; pA[2 * q + 1] = h1 * w2j;
                upk2(accB[q], h0, h1);
                h0 = (h0 > 0.f) ? h0 : 0.2f * h0;
                h1 = (h1 > 0.f) ? h1 : 0.2f * h1;
                pB[2 * q] = h0 * w2j; pB[2 * q + 1] = h1 * w2j;
            }
        } else {
#pragma unroll
            for (int n = 0; n < NN; n++) { pA[n] = 0.f; pB[n] = 0.f; }
        }
        // ---- packed score reductions over j ----
#pragma unroll
        for (int q = 0; q < 6; q++) {
            ull v = warp_sum2(pk2(pA[2 * q], pA[2 * q + 1]));
            if (lane == 0) {
                float lo, hi; upk2(v, lo, hi);
                redSA[(2 * q) * 4 + warp] = lo;
                redSA[(2 * q + 1) * 4 + warp] = hi;
            }
            v = warp_sum2(pk2(pB[2 * q], pB[2 * q + 1]));
            if (lane == 0) {
                float lo, hi; upk2(v, lo, hi);
                redSB[(2 * q) * 4 + warp] = lo;
                redSB[(2 * q + 1) * 4 + warp] = hi;
            }
        }
        __syncthreads();
        if (tid < NN)
            scSA[tid] = redSA[tid * 4] + redSA[tid * 4 + 1] + redSA[tid * 4 + 2] + redSA[tid * 4 + 3];
        else if (tid >= 32 && tid < 32 + NN) {
            int n = tid - 32;
            scSB[n] = redSB[n * 4] + redSB[n * 4 + 1] + redSB[n * 4 + 2] + redSB[n * 4 + 3];
        }
        __syncthreads();
        // ---- softmax over 12 on sparse threads (warp0 -> A, warp1 -> B) ----
        if (tid < NN) {
            float mx = scSA[0];
#pragma unroll
            for (int n = 1; n < NN; n++) mx = fmaxf(mx, scSA[n]);
            float ssum = 0.f;
#pragma unroll
            for (int n = 0; n < NN; n++) ssum += __expf(scSA[n] - mx);
            attA[tid] = __expf(scSA[tid] - mx) / ssum;
        } else if (tid >= 32 && tid < 32 + NN) {
            int n = tid - 32;
            float mx = scSB[0];
#pragma unroll
            for (int k = 1; k < NN; k++) mx = fmaxf(mx, scSB[k]);
            float ssum = 0.f;
#pragma unroll
            for (int k = 0; k < NN; k++) ssum += __expf(scSB[k] - mx);
            attB[n] = __expf(scSB[n] - mx) / ssum;
        }
        __syncthreads();
        // ---- weighted sums ----
        float totA = 0.f, totB = 0.f;
        if (j < DD) {
            const float4* a4 = reinterpret_cast<const float4*>(attA);
            const float4* b4 = reinterpret_cast<const float4*>(attB);
            float4 wa0 = a4[0], wa1 = a4[1], wa2 = a4[2];
            float4 wb0 = b4[0], wb1 = b4[1], wb2 = b4[2];
            totA = wa0.x * VsA[0 * DD + j];
            totA = fmaf(wa0.y, VsA[1 * DD + j], totA);
            totA = fmaf(wa0.z, VsA[2 * DD + j], totA);
            totA = fmaf(wa0.w, VsA[3 * DD + j], totA);
            totA = fmaf(wa1.x, VsA[4 * DD + j], totA);
            totA = fmaf(wa1.y, VsA[5 * DD + j], totA);
            totA = fmaf(wa1.z, VsA[6 * DD + j], totA);
            totA = fmaf(wa1.w, VsA[7 * DD + j], totA);
            totA = fmaf(wa2.x, VsA[8 * DD + j], totA);
            totA = fmaf(wa2.y, VsA[9 * DD + j], totA);
            totA = fmaf(wa2.z, VsA[10 * DD + j], totA);
            totA = fmaf(wa2.w, VsA[11 * DD + j], totA);
            totB = wb0.x * VsB[0 * DD + j];
            totB = fmaf(wb0.y, VsB[1 * DD + j], totB);
            totB = fmaf(wb0.z, VsB[2 * DD + j], totB);
            totB = fmaf(wb0.w, VsB[3 * DD + j], totB);
            totB = fmaf(wb1.x, VsB[4 * DD + j], totB);
            totB = fmaf(wb1.y, VsB[5 * DD + j], totB);
            totB = fmaf(wb1.z, VsB[6 * DD + j], totB);
            totB = fmaf(wb1.w, VsB[7 * DD + j], totB);
            totB = fmaf(wb2.x, VsB[8 * DD + j], totB);
            totB = fmaf(wb2.y, VsB[9 * DD + j], totB);
            totB = fmaf(wb2.z, VsB[10 * DD + j], totB);
            totB = fmaf(wb2.w, VsB[11 * DD + j], totB);
        }
        if (NORM) {
            ull sq = warp_sum2(pk2(totA * totA, totB * totB));
            if (lane == 0) {
                float lo, hi; upk2(sq, lo, hi);
                red2A[warp] = lo; red2B[warp] = hi;
            }
            __syncthreads();
            float nA = sqrtf(red2A[0] + red2A[1] + red2A[2] + red2A[3]);
            float nB = sqrtf(red2B[0] + red2B[1] + red2B[2] + red2B[3]);
            if (j < DD) {
                outv[(size_t)uA * DD + j] = totA * (1.f / fmaxf(nA, 1e-12f));
                outv[(size_t)uB * DD + j] = totB * (1.f / fmaxf(nB, 1e-12f));
            }
        } else {
            if (j < DD) {
                outv[(size_t)uA * DD + j] = totA;
                outv[(size_t)uB * DD + j] = totB;
            }
        }
        __syncthreads();
    }
}

// ===========================================================================
// Target neighbor attention, TWO units per thread. K = 2D = 200.
//   cat[m] = [ t .* V[m] , sl + V[m] ];  a = softmax_m(tanh(cat@W3) . w4)
//   out = l2norm((sum_m a[m] V[m] + t0) * 0.5)
// ===========================================================================
template <int UPB>
__global__ void __launch_bounds__(128) tar_att_kernel(
    const float* __restrict__ t_in, const float* __restrict__ sl_base,
    const float* __restrict__ tneigh, const float* __restrict__ t0v,
    const float* __restrict__ W3, const float* __restrict__ w4,
    float* __restrict__ outv, int nunits)
{
    extern __shared__ float sm[];
    float* W3s   = sm;            // 20000
    float* w4s   = sm + 20000;    // 104
    float* VsA   = sm + 20104;    // 1200
    float* VsB   = sm + 21304;    // 1200
    float* XtA   = sm + 22504;    // 3200 (200 rows of 16)
    float* XtB   = sm + 25704;    // 3200
    float* attA  = sm + 28904;    // 16
    float* attB  = sm + 28920;    // 16
    float* scSA  = sm + 28936;    // 16
    float* scSB  = sm + 28952;    // 16
    float* redSA = sm + 28968;    // 48
    float* redSB = sm + 29016;    // 48
    float* red2A = sm + 29064;    // 8
    float* red2B = sm + 29072;    // 8  total 29080 floats = 116320 B

    const int tid  = threadIdx.x;
    const int lane = tid & 31, warp = tid >> 5;
    const int j = tid;

    {
        const float4* W4 = reinterpret_cast<const float4*>(W3);
        float4* W3s4 = reinterpret_cast<float4*>(W3s);
        for (int i = tid; i < 2 * DD * DD / 4; i += 128) W3s4[i] = W4[i];
        if (tid < DD) w4s[tid] = w4[tid];
    }
    __syncthreads();

    const int u0 = blockIdx.x * UPB;
    for (int u = u0; u < u0 + UPB; u += 2) {
        const int uA = u, uB = u + 1;
        const int bA = uA / SS, bB = uB / SS;
        {
            const float4* ngA = reinterpret_cast<const float4*>(tneigh + (size_t)uA * (MM * DD));
            const float4* ngB = reinterpret_cast<const float4*>(tneigh + (size_t)uB * (MM * DD));
            float4* vA4 = reinterpret_cast<float4*>(VsA);
            float4* vB4 = reinterpret_cast<float4*>(VsB);
#pragma unroll
            for (int k = 0; k < 3; k++) {
                int i = tid + k * 128;
                if (i < MM * DD / 4) { vA4[i] = ngA[i]; vB4[i] = ngB[i]; }
            }
        }
        __syncthreads();
        // build Xt rows (k = 0..199): k<100: t.*V ; k>=100: sl+V
#pragma unroll
        for (int it = 0; it < 2; it++) {
            int k = tid + it * 128;
            if (k < 2 * DD) {
                int dd = (k < DD) ? k : (k - DD);
                float rA[MM], rB[MM];
                if (k < DD) {
                    float tA = __ldg(t_in + (size_t)uA * DD + dd);
                    float tB = __ldg(t_in + (size_t)uB * DD + dd);
#pragma unroll
                    for (int m = 0; m < MM; m++) {
                        rA[m] = tA * VsA[m * DD + dd];
                        rB[m] = tB * VsB[m * DD + dd];
                    }
                } else {
                    float lA = __ldg(sl_base + (size_t)bA * (LL * DD) + dd);
                    float lB = __ldg(sl_base + (size_t)bB * (LL * DD) + dd);
#pragma unroll
                    for (int m = 0; m < MM; m++) {
                        rA[m] = lA + VsA[m * DD + dd];
                        rB[m] = lB + VsB[m * DD + dd];
                    }
                }
                float4* xa = reinterpret_cast<float4*>(XtA + k * 16);
                float4* xb = reinterpret_cast<float4*>(XtB + k * 16);
                xa[0] = make_float4(rA[0], rA[1], rA[2], rA[3]);
                xa[1] = make_float4(rA[4], rA[5], rA[6], rA[7]);
                xa[2] = make_float4(rA[8], rA[9], rA[10], rA[11]);
                xb[0] = make_float4(rB[0], rB[1], rB[2], rB[3]);
                xb[1] = make_float4(rB[4], rB[5], rB[6], rB[7]);
                xb[2] = make_float4(rB[8], rB[9], rB[10], rB[11]);
            }
        }
        __syncthreads();

        float pA[MM], pB[MM];
        if (j < DD) {
            ull aA0 = 0, aA1 = 0, aA2 = 0, aA3 = 0, aA4 = 0, aA5 = 0;
            ull aB0 = 0, aB1 = 0, aB2 = 0, aB3 = 0, aB4 = 0, aB5 = 0;
            const ulonglong2* XA = reinterpret_cast<const ulonglong2*>(XtA);
            const ulonglong2* XB = reinterpret_cast<const ulonglong2*>(XtB);
#pragma unroll 4
            for (int k = 0; k < 2 * DD; ++k) {
                float w = W3s[k * DD + j];
                ull ww = pk2(w, w);
                ulonglong2 x0 = XA[k * 4 + 0], x1 = XA[k * 4 + 1], x2 = XA[k * 4 + 2];
                ulonglong2 y0 = XB[k * 4 + 0], y1 = XB[k * 4 + 1], y2 = XB[k * 4 + 2];
                aA0 = ffma2(x0.x, ww, aA0); aA1 = ffma2(x0.y, ww, aA1);
                aA2 = ffma2(x1.x, ww, aA2); aA3 = ffma2(x1.y, ww, aA3);
                aA4 = ffma2(x2.x, ww, aA4); aA5 = ffma2(x2.y, ww, aA5);
                aB0 = ffma2(y0.x, ww, aB0); aB1 = ffma2(y0.y, ww, aB1);
                aB2 = ffma2(y1.x, ww, aB2); aB3 = ffma2(y1.y, ww, aB3);
                aB4 = ffma2(y2.x, ww, aB4); aB5 = ffma2(y2.y, ww, aB5);
            }
            const float w4j = w4s[j];
            ull accA[6] = {aA0, aA1, aA2, aA3, aA4, aA5};
            ull accB[6] = {aB0, aB1, aB2, aB3, aB4, aB5};
#pragma unroll
            for (int q = 0; q < 6; q++) {
                float h0, h1;
                upk2(accA[q], h0, h1);
                pA[2 * q] = tanhf(h0) * w4j; pA[2 * q + 1] = tanhf(h1) * w4j;
                upk2(accB[q], h0, h1);
                pB[2 * q] = tanhf(h0) * w4j; pB[2 * q + 1] = tanhf(h1) * w4j;
            }
        } else {
#pragma unroll
            for (int m = 0; m < MM; m++) { pA[m] = 0.f; pB[m] = 0.f; }
        }
#pragma unroll
        for (int q = 0; q < 6; q++) {
            ull v = warp_sum2(pk2(pA[2 * q], pA[2 * q + 1]));
            if (lane == 0) {
                float lo, hi; upk2(v, lo, hi);
                redSA[(2 * q) * 4 + warp] = lo;
                redSA[(2 * q + 1) * 4 + warp] = hi;
            }
            v = warp_sum2(pk2(pB[2 * q], pB[2 * q + 1]));
            if (lane == 0) {
                float lo, hi; upk2(v, lo, hi);
                redSB[(2 * q) * 4 + warp] = lo;
                redSB[(2 * q + 1) * 4 + warp] = hi;
            }
        }
        __syncthreads();
        if (tid < MM)
            scSA[tid] = redSA[tid * 4] + redSA[tid * 4 + 1] + redSA[tid * 4 + 2] + redSA[tid * 4 + 3];
        else if (tid >= 32 && tid < 32 + MM) {
            int m = tid - 32;
            scSB[m] = redSB[m * 4] + redSB[m * 4 + 1] + redSB[m * 4 + 2] + redSB[m * 4 + 3];
        }
        __syncthreads();
        if (tid < MM) {
            float mx = scSA[0];
#pragma unroll
            for (int m = 1; m < MM; m++) mx = fmaxf(mx, scSA[m]);
            float ssum = 0.f;
#pragma unroll
            for (int m = 0; m < MM; m++) ssum += __expf(scSA[m] - mx);
            attA[tid] = __expf(scSA[tid] - mx) / ssum;
        } else if (tid >= 32 && tid < 32 + MM) {
            int m = tid - 32;
            float mx = scSB[0];
#pragma unroll
            for (int k = 1; k < MM; k++) mx = fmaxf(mx, scSB[k]);
            float ssum = 0.f;
#pragma unroll
            for (int k = 0; k < MM; k++) ssum += __expf(scSB[k] - mx);
            attB[m] = __expf(scSB[m] - mx) / ssum;
        }
        __syncthreads();
        float totA = 0.f, totB = 0.f;
        if (j < DD) {
            const float4* a4 = reinterpret_cast<const float4*>(attA);
            const float4* b4 = reinterpret_cast<const float4*>(attB);
            float4 wa0 = a4[0], wa1 = a4[1], wa2 = a4[2];
            float4 wb0 = b4[0], wb1 = b4[1], wb2 = b4[2];
            float wA[MM] = {wa0.x, wa0.y, wa0.z, wa0.w, wa1.x, wa1.y, wa1.z, wa1.w, wa2.x, wa2.y, wa2.z, wa2.w};
            float wB[MM] = {wb0.x, wb0.y, wb0.z, wb0.w, wb1.x, wb1.y, wb1.z, wb1.w, wb2.x, wb2.y, wb2.z, wb2.w};
#pragma unroll
            for (int m = 0; m < MM; m++) {
                totA = fmaf(wA[m], VsA[m * DD + j], totA);
                totB = fmaf(wB[m], VsB[m * DD + j], totB);
            }
            totA = (totA + __ldg(t0v + (size_t)uA * DD + j)) * 0.5f;
            totB = (totB + __ldg(t0v + (size_t)uB * DD + j)) * 0.5f;
        }
        ull sq = warp_sum2(pk2(totA * totA, totB * totB));
        if (lane == 0) {
            float lo, hi; upk2(sq, lo, hi);
            red2A[warp] = lo; red2B[warp] = hi;
        }
        __syncthreads();
        float nA = sqrtf(red2A[0] + red2A[1] + red2A[2] + red2A[3]);
        float nB = sqrtf(red2B[0] + red2B[1] + red2B[2] + red2B[3]);
        if (j < DD) {
            outv[(size_t)uA * DD + j] = totA * (1.f / fmaxf(nA, 1e-12f));
            outv[(size_t)uB * DD + j] = totB * (1.f / fmaxf(nB, 1e-12f));
        }
        __syncthreads();
    }
}

// ===========================================================================
// Output assembly (unchanged from round 1).
// ===========================================================================
__global__ void out_kernel(const float* __restrict__ ss, const float* __restrict__ e1,
                           const float* __restrict__ e2, const float* __restrict__ t0,
                           const float* __restrict__ t1, const float* __restrict__ t2,
                           float4* __restrict__ out4)
{
    const int SESS4 = 3 * BB * SS * LL * (DD / 4);
    const int TAR4  = 10 * BB * SS * (DD / 4);
    int idx = blockIdx.x * blockDim.x + threadIdx.x;
    if (idx < SESS4) {
        int r = idx % 25;
        int q = idx / 25;
        int l = q % LL;
        int t = q / LL;
        int bb = t / SS;
        int layer = bb >> 7;
        int b = bb & (BB - 1);
        const float* src = (layer == 0) ? ss : ((layer == 1) ? e1 : e2);
        out4[idx] = reinterpret_cast<const float4*>(src + ((size_t)b * LL + l) * DD)[r];
    } else if (idx < SESS4 + TAR4) {
        int jj = idx - SESS4;
        int k = jj / (BB * SS * (DD / 4));
        int i = jj % (BB * SS * (DD / 4));
        int km = k % 5;
        const float* src = (km == 4) ? t2 : ((km & 1) ? t1 : t0);
        out4[idx] = reinterpret_cast<const float4*>(src)[i];
    }
}

// ===========================================================================
extern "C" void kernel_launch(void* const* d_in, const int* in_sizes, int n_in,
                              void* d_out, int out_size)
{
    const float* sess_self      = (const float*)d_in[0];
    const float* sess_neighbor  = (const float*)d_in[1];
    const float* sess_neighbor2 = (const float*)d_in[2];
    const float* tar_self       = (const float*)d_in[3];
    const float* tar_neighbor   = (const float*)d_in[4];
    const float* w1             = (const float*)d_in[5];
    const float* w2             = (const float*)d_in[6];
    const float* w3             = (const float*)d_in[7];
    const float* w4             = (const float*)d_in[8];
    float* out = (float*)d_out;

    float *emb1, *emb2, *sn2, *t1, *t2;
    cudaGetSymbolAddress((void**)&emb1, g_emb1);
    cudaGetSymbolAddress((void**)&emb2, g_emb2);
    cudaGetSymbolAddress((void**)&sn2,  g_sn2);
    cudaGetSymbolAddress((void**)&t1,   g_t1);
    cudaGetSymbolAddress((void**)&t2,   g_t2);

    const int SMEM_SESS = 15880 * 4;   // 63,520 B -> 3 blocks/SM
    const int SMEM_TAR  = 29080 * 4;   // 116,320 B -> 1 block/SM
    cudaFuncSetAttribute(sess_att_kernel<true, 4>,
                         cudaFuncAttributeMaxDynamicSharedMemorySize, SMEM_SESS);
    cudaFuncSetAttribute(sess_att_kernel<false, 16>,
                         cudaFuncAttributeMaxDynamicSharedMemorySize, SMEM_SESS);
    cudaFuncSetAttribute(tar_att_kernel<4>,
                         cudaFuncAttributeMaxDynamicSharedMemorySize, SMEM_TAR);

    const int U1 = BB * LL;        // 6400
    const int U2 = BB * LL * NN;   // 76800
    const int UT = BB * SS;        // 2560

    // K1: layer-0 session attention -> emb1 (normalized)
    sess_att_kernel<true, 4><<<U1 / 4, 128, SMEM_SESS>>>(
        sess_self, sess_neighbor, w1, w2, emb1, U1);

    // K2: 2-hop aggregation (dominant) -> sn2
    sess_att_kernel<false, 16><<<U2 / 16, 128, SMEM_SESS>>>(
        sess_neighbor, sess_neighbor2, w1, w2, sn2, U2);

    // K3: layer-0 target attention (sess_last = emb1[b, l=0]) -> t1
    tar_att_kernel<4><<<UT / 4, 128, SMEM_TAR>>>(
        tar_self, emb1, tar_neighbor, tar_self, w3, w4, t1, UT);

    // K4: layer-1 session attention -> emb2
    sess_att_kernel<true, 4><<<U1 / 4, 128, SMEM_SESS>>>(
        emb1, sn2, w1 + DD * DD, w2 + DD, emb2, U1);

    // K5: layer-1 target attention (t = t1, sess_last = sess_self[b, l=0]) -> t2
    tar_att_kernel<4><<<UT / 4, 128, SMEM_TAR>>>(
        t1, sess_self, tar_neighbor, tar_self, w3 + 2 * DD * DD, w4 + DD, t2, UT);

    // K6: assemble output
    const int TOT4 = 3 * BB * SS * LL * (DD / 4) + 10 * BB * SS * (DD / 4);
    out_kernel<<<(TOT4 + 255) / 256, 256>>>(sess_self, emb1, emb2,
                                            tar_self, t1, t2, (float4*)out);
}